// round 5
// baseline (speedup 1.0000x reference)
#include <cuda_runtime.h>
#include <math.h>

#define N 512
#define D 256
#define BT 32
#define NBLK_D 136            // 16*17/2 triangle of 32x32 tiles
#define NBLK_T 128            // triplet blocks: 4 warps = 4 anchors each
#define FULL 0xFFFFFFFFu

// __device__ scratch (allocation-free rule)
__device__ float g_dist[N * N];
__device__ float g_psum[NBLK_T];
__device__ float g_pcnt[NBLK_T];
__device__ int   g_done = 0;

// ---------------------------------------------------------------------------
// Kernel 1: fused sq-norms + symmetric distances.
// 136 triangle blocks, 256 threads, 32x32 tile, 1x4 register strip/thread.
// ---------------------------------------------------------------------------
__global__ void __launch_bounds__(256)
dist_kernel(const float* __restrict__ x) {
    __shared__ float As[BT][36];      // [m][k], pad 36 (16B-aligned rows)
    __shared__ float Bs[BT][36];      // [k][n], pad 36
    __shared__ float sqi[BT];
    __shared__ float sqj[BT];

    const int t = threadIdx.x;        // 0..255
    const int lane = t & 31;
    const int w = t >> 5;             // 0..7

    // triangle decode (bi >= bj)
    int b = blockIdx.x;
    int bi = (int)((sqrtf(8.f * (float)b + 1.f) - 1.f) * 0.5f);
    while ((bi + 1) * (bi + 2) / 2 <= b) bi++;
    while (bi * (bi + 1) / 2 > b) bi--;
    const int bj = b - bi * (bi + 1) / 2;
    const int i0 = bi * BT;
    const int j0 = bj * BT;

    // --- sq norms: warp w handles 8 of the 64 rows ---
#pragma unroll
    for (int rr = 0; rr < 8; rr++) {
        int r = w * 8 + rr;                          // 0..63
        int gr = (r < 32) ? (i0 + r) : (j0 + r - 32);
        const float* row = x + gr * D;
        float s = 0.f;
#pragma unroll
        for (int c = 0; c < 8; c++) { float v = row[lane + 32 * c]; s += v * v; }
#pragma unroll
        for (int o = 16; o > 0; o >>= 1) s += __shfl_down_sync(FULL, s, o);
        if (lane == 0) { if (r < 32) sqi[r] = s; else sqj[r - 32] = s; }
    }

    // --- loaders ---
    const int lrA = t >> 3;           // A row 0..31
    const int lkA = (t & 7) * 4;      // A k-offset 0,4,..,28
    const int jrB = t & 31;           // B row (j) 0..31
    const int kqB = (t >> 5) * 4;     // B k-quad 0,4,..,28

    // --- compute mapping: 1 row x 4 cols ---
    const int row = t >> 3;           // 0..31
    const int c4  = (t & 7) * 4;      // j offset 0,4,..,28

    float acc0 = 0.f, acc1 = 0.f, acc2 = 0.f, acc3 = 0.f;

    const float* pa = x + (i0 + lrA) * D + lkA;
    const float* pb = x + (j0 + jrB) * D + kqB;

    float4 va = *reinterpret_cast<const float4*>(pa);
    float4 vb = *reinterpret_cast<const float4*>(pb);

#pragma unroll
    for (int ch = 0; ch < D / BT; ch++) {
        __syncthreads();
        *reinterpret_cast<float4*>(&As[lrA][lkA]) = va;       // STS.128
        Bs[kqB + 0][jrB] = vb.x;                              // conflict-free
        Bs[kqB + 1][jrB] = vb.y;
        Bs[kqB + 2][jrB] = vb.z;
        Bs[kqB + 3][jrB] = vb.w;
        __syncthreads();

        if (ch < D / BT - 1) {        // register prefetch of next chunk
            va = *reinterpret_cast<const float4*>(pa + (ch + 1) * BT);
            vb = *reinterpret_cast<const float4*>(pb + (ch + 1) * BT);
        }

#pragma unroll
        for (int k = 0; k < BT; k++) {
            float  a  = As[row][k];
            float4 bq = *reinterpret_cast<const float4*>(&Bs[k][c4]);
            acc0 += a * bq.x; acc1 += a * bq.y;
            acc2 += a * bq.z; acc3 += a * bq.w;
        }
    }

    // epilogue: dist + mirror
    const int ig = i0 + row;
    const float si = sqi[row];
    float d0 = sqrtf(fmaxf(si + sqj[c4 + 0] - 2.f * acc0, 1e-16f));
    float d1 = sqrtf(fmaxf(si + sqj[c4 + 1] - 2.f * acc1, 1e-16f));
    float d2 = sqrtf(fmaxf(si + sqj[c4 + 2] - 2.f * acc2, 1e-16f));
    float d3 = sqrtf(fmaxf(si + sqj[c4 + 3] - 2.f * acc3, 1e-16f));

    *reinterpret_cast<float4*>(g_dist + ig * N + j0 + c4) =
        make_float4(d0, d1, d2, d3);
    // mirror (diagonal tiles: same-value duplicate writes, benign)
    g_dist[(j0 + c4 + 0) * N + ig] = d0;
    g_dist[(j0 + c4 + 1) * N + ig] = d1;
    g_dist[(j0 + c4 + 2) * N + ig] = d2;
    g_dist[(j0 + c4 + 3) * N + ig] = d3;
}

// ---------------------------------------------------------------------------
// Kernel 2: warp-per-anchor triplet reduction. 128 blocks x 128 threads.
// No block syncs in the hot path; fused final reduce via last-block elect.
// ---------------------------------------------------------------------------
__global__ void __launch_bounds__(128)
triplet_kernel(const int* __restrict__ labels, float* __restrict__ out) {
    __shared__ int   lab[N];
    __shared__ float sdv[4][N];       // per-warp private dist row
    __shared__ float sred[4];
    __shared__ int   cred[4];
    __shared__ float fsred[4];
    __shared__ float fcred[4];
    __shared__ int   s_last;

    const int t = threadIdx.x;        // 0..127
    const int lane = t & 31;
    const int w = t >> 5;             // 0..3
    const int a = blockIdx.x * 4 + w; // this warp's anchor

    reinterpret_cast<int4*>(lab)[t] = reinterpret_cast<const int4*>(labels)[t];
    __syncthreads();

    const int li = lab[a];

    // load dist row: 16 regs + private smem copy; build negative bitmask
    float dv[16];
    unsigned nm = 0;
#pragma unroll
    for (int c = 0; c < 16; c++) {
        float v = g_dist[a * N + c * 32 + lane];
        dv[c] = v;
        sdv[w][c * 32 + lane] = v;
        if (lab[c * 32 + lane] != li) nm |= (1u << c);
    }

    float sum = 0.f;
    int cnt = 0;

    for (int c = 0; c < 16; c++) {    // candidate-positive chunks
        int jj = c * 32 + lane;
        unsigned pm = __ballot_sync(FULL, (lab[jj] == li) && (jj != a));
        while (pm) {
            int bit = __ffs(pm) - 1;
            pm &= pm - 1;
            float aa = sdv[w][c * 32 + bit] + 1.0f;   // smem broadcast
#pragma unroll
            for (int ck = 0; ck < 16; ck++) {
                if ((nm >> ck) & 1u) {
                    float v = aa - dv[ck];
                    if (v > 0.f) sum += v;
                    if (v > 1e-16f) cnt++;
                }
            }
        }
    }

    // warp reduce -> block combine (deterministic)
#pragma unroll
    for (int o = 16; o > 0; o >>= 1) {
        sum += __shfl_down_sync(FULL, sum, o);
        cnt += __shfl_down_sync(FULL, cnt, o);
    }
    if (lane == 0) { sred[w] = sum; cred[w] = cnt; }
    __syncthreads();
    if (t == 0) {
        float s = sred[0] + sred[1] + sred[2] + sred[3];
        int   c = cred[0] + cred[1] + cred[2] + cred[3];
        g_psum[blockIdx.x] = s;
        g_pcnt[blockIdx.x] = (float)c;
        __threadfence();
        int old = atomicAdd(&g_done, 1);
        s_last = (old == NBLK_T - 1) ? 1 : 0;
    }
    __syncthreads();

    if (s_last) {                     // final reduction over 128 partials
        __threadfence();
        float s = g_psum[t];
        float c = g_pcnt[t];
#pragma unroll
        for (int o = 16; o > 0; o >>= 1) {
            s += __shfl_down_sync(FULL, s, o);
            c += __shfl_down_sync(FULL, c, o);
        }
        if (lane == 0) { fsred[w] = s; fcred[w] = c; }
        __syncthreads();
        if (t == 0) {
            float S = fsred[0] + fsred[1] + fsred[2] + fsred[3];
            float C = fcred[0] + fcred[1] + fcred[2] + fcred[3];
            out[0] = S / (C + 1e-16f);
            g_done = 0;               // reset for next graph replay
        }
    }
}

// ---------------------------------------------------------------------------
extern "C" void kernel_launch(void* const* d_in, const int* in_sizes, int n_in,
                              void* d_out, int out_size) {
    const float* x      = (const float*)d_in[0];   // (512, 256) float32
    const int*   labels = (const int*)d_in[1];     // (512,) int32
    float* out = (float*)d_out;

    dist_kernel<<<NBLK_D, 256>>>(x);
    triplet_kernel<<<NBLK_T, 128>>>(labels, out);
}

// round 6
// speedup vs baseline: 1.2365x; 1.2365x over previous
#include <cuda_runtime.h>
#include <math.h>

#define N 512
#define D 256
#define BT 32
#define NBLK_D 136            // 16*17/2 triangle of 32x32 tiles
#define NBLK_T 512            // triplet blocks: one anchor each
#define FULL 0xFFFFFFFFu

// __device__ scratch (allocation-free rule)
__device__ float g_dist[N * N];
__device__ float g_psum[NBLK_T];
__device__ float g_pcnt[NBLK_T];
__device__ int   g_done = 0;

// ---------------------------------------------------------------------------
// Kernel 1: fused sq-norms + symmetric distances.
// 136 triangle blocks, 256 threads, 32x32 tile, 2x2 register tile.
// Both A and B stored k-major [k][34]: float2 reads, 2 crossbar phases/warp-k.
// ---------------------------------------------------------------------------
__global__ void __launch_bounds__(256)
dist_kernel(const float* __restrict__ x) {
    __shared__ float As[BT][34];      // [k][m], stride 34 (even -> 8B aligned)
    __shared__ float Bs[BT][34];      // [k][n]
    __shared__ float sqi[BT];
    __shared__ float sqj[BT];

    const int t = threadIdx.x;        // 0..255
    const int lane = t & 31;
    const int w = t >> 5;             // 0..7

    // triangle decode (bi >= bj)
    int b = blockIdx.x;
    int bi = (int)((sqrtf(8.f * (float)b + 1.f) - 1.f) * 0.5f);
    while ((bi + 1) * (bi + 2) / 2 <= b) bi++;
    while (bi * (bi + 1) / 2 > b) bi--;
    const int bj = b - bi * (bi + 1) / 2;
    const int i0 = bi * BT;
    const int j0 = bj * BT;

    // --- sq norms: warp w handles 8 of the 64 rows ---
#pragma unroll
    for (int rr = 0; rr < 8; rr++) {
        int r = w * 8 + rr;                          // 0..63
        int gr = (r < 32) ? (i0 + r) : (j0 + r - 32);
        const float* row = x + gr * D;
        float s = 0.f;
#pragma unroll
        for (int c = 0; c < 8; c++) { float v = row[lane + 32 * c]; s += v * v; }
#pragma unroll
        for (int o = 16; o > 0; o >>= 1) s += __shfl_down_sync(FULL, s, o);
        if (lane == 0) { if (r < 32) sqi[r] = s; else sqj[r - 32] = s; }
    }

    // --- loader mapping ---
    const int lr = t >> 3;            // row 0..31
    const int lk = (t & 7) * 4;       // k offset 0,4,..,28

    // --- compute mapping: 2x2 ---
    const int tx = t & 15;            // j pair
    const int ty = t >> 4;            // i pair

    float acc00 = 0.f, acc01 = 0.f, acc10 = 0.f, acc11 = 0.f;

    const float* pa = x + (i0 + lr) * D + lk;
    const float* pb = x + (j0 + lr) * D + lk;

    float4 va = *reinterpret_cast<const float4*>(pa);
    float4 vb = *reinterpret_cast<const float4*>(pb);

#pragma unroll
    for (int ch = 0; ch < D / BT; ch++) {
        __syncthreads();
        As[lk + 0][lr] = va.x; As[lk + 1][lr] = va.y;
        As[lk + 2][lr] = va.z; As[lk + 3][lr] = va.w;
        Bs[lk + 0][lr] = vb.x; Bs[lk + 1][lr] = vb.y;
        Bs[lk + 2][lr] = vb.z; Bs[lk + 3][lr] = vb.w;
        __syncthreads();

        if (ch < D / BT - 1) {        // register prefetch of next chunk
            va = *reinterpret_cast<const float4*>(pa + (ch + 1) * BT);
            vb = *reinterpret_cast<const float4*>(pb + (ch + 1) * BT);
        }

#pragma unroll
        for (int k = 0; k < BT; k++) {
            float2 a = *reinterpret_cast<const float2*>(&As[k][2 * ty]);
            float2 bq = *reinterpret_cast<const float2*>(&Bs[k][2 * tx]);
            acc00 += a.x * bq.x; acc01 += a.x * bq.y;
            acc10 += a.y * bq.x; acc11 += a.y * bq.y;
        }
    }

    // epilogue: dist + mirror
    const int ig = i0 + 2 * ty;
    const int jg = j0 + 2 * tx;
    const float si0 = sqi[2 * ty], si1 = sqi[2 * ty + 1];
    const float sj0 = sqj[2 * tx], sj1 = sqj[2 * tx + 1];

    float d00 = sqrtf(fmaxf(si0 + sj0 - 2.f * acc00, 1e-16f));
    float d01 = sqrtf(fmaxf(si0 + sj1 - 2.f * acc01, 1e-16f));
    float d10 = sqrtf(fmaxf(si1 + sj0 - 2.f * acc10, 1e-16f));
    float d11 = sqrtf(fmaxf(si1 + sj1 - 2.f * acc11, 1e-16f));

    *reinterpret_cast<float2*>(g_dist + (ig    ) * N + jg) = make_float2(d00, d01);
    *reinterpret_cast<float2*>(g_dist + (ig + 1) * N + jg) = make_float2(d10, d11);
    // mirror (diagonal tiles: same-value duplicate writes, benign)
    g_dist[(jg    ) * N + ig    ] = d00;
    g_dist[(jg + 1) * N + ig    ] = d01;
    g_dist[(jg    ) * N + ig + 1] = d10;
    g_dist[(jg + 1) * N + ig + 1] = d11;
}

// ---------------------------------------------------------------------------
// Kernel 2: triplet reduction, 512 blocks (1 anchor) x 512 threads (1 elem).
// Compaction of positives, branch-free hinge, fused final reduce.
// ---------------------------------------------------------------------------
__global__ void __launch_bounds__(512)
triplet_kernel(const int* __restrict__ labels, float* __restrict__ out) {
    __shared__ float drow[N];
    __shared__ int   lab[N];
    __shared__ int   segcnt[16];
    __shared__ int   posj[N];
    __shared__ int   s_npos;
    __shared__ float sred[16];
    __shared__ int   cred[16];
    __shared__ float fsred[16];
    __shared__ float fcred[16];
    __shared__ int   s_last;

    const int i = blockIdx.x;         // anchor
    const int t = threadIdx.x;        // 0..511
    const int lane = t & 31;
    const int w = t >> 5;             // 0..15

    drow[t] = g_dist[i * N + t];
    lab[t]  = labels[t];
    __syncthreads();

    const int li = lab[i];
    const bool m0 = (lab[t] == li) && (t != i);

    // deterministic compaction of positives
    unsigned b0 = __ballot_sync(FULL, m0);
    if (lane == 0) segcnt[w] = __popc(b0);
    __syncthreads();
    if (m0) {
        int off = 0;
#pragma unroll
        for (int s = 0; s < 15; s++) if (s < w) off += segcnt[s];
        off += __popc(b0 & ((1u << lane) - 1u));
        posj[off] = t;
    }
    if (t == 0) {
        int tot = 0;
#pragma unroll
        for (int s = 0; s < 16; s++) tot += segcnt[s];
        s_npos = tot;
    }
    __syncthreads();

    const int npos = s_npos;
    const float d0 = drow[t];
    const bool n0 = (lab[t] != li);

    float sum = 0.f;
    int cnt = 0;
    for (int p = 0; p < npos; p++) {
        float aa = drow[posj[p]] + 1.0f;     // d_ij + margin, smem broadcast
        float v = aa - d0;
        v = n0 ? v : -1.0f;                  // mask invalid (predicated SEL)
        if (v > 0.f) sum += v;
        if (v > 1e-16f) cnt++;
    }

    // deterministic block reduction (16 warps)
#pragma unroll
    for (int o = 16; o > 0; o >>= 1) {
        sum += __shfl_down_sync(FULL, sum, o);
        cnt += __shfl_down_sync(FULL, cnt, o);
    }
    if (lane == 0) { sred[w] = sum; cred[w] = cnt; }
    __syncthreads();
    if (t == 0) {
        float s = 0.f; int c = 0;
#pragma unroll
        for (int k = 0; k < 16; k++) { s += sred[k]; c += cred[k]; }
        g_psum[i] = s;
        g_pcnt[i] = (float)c;
        __threadfence();
        int old = atomicAdd(&g_done, 1);
        s_last = (old == NBLK_T - 1) ? 1 : 0;
    }
    __syncthreads();

    if (s_last) {                     // final reduction over 512 partials
        __threadfence();
        float s = g_psum[t];
        float c = g_pcnt[t];
#pragma unroll
        for (int o = 16; o > 0; o >>= 1) {
            s += __shfl_down_sync(FULL, s, o);
            c += __shfl_down_sync(FULL, c, o);
        }
        if (lane == 0) { fsred[w] = s; fcred[w] = c; }
        __syncthreads();
        if (t == 0) {
            float S = 0.f, C = 0.f;
#pragma unroll
            for (int k = 0; k < 16; k++) { S += fsred[k]; C += fcred[k]; }
            out[0] = S / (C + 1e-16f);
            g_done = 0;               // reset for next graph replay
        }
    }
}

// ---------------------------------------------------------------------------
extern "C" void kernel_launch(void* const* d_in, const int* in_sizes, int n_in,
                              void* d_out, int out_size) {
    const float* x      = (const float*)d_in[0];   // (512, 256) float32
    const int*   labels = (const int*)d_in[1];     // (512,) int32
    float* out = (float*)d_out;

    dist_kernel<<<NBLK_D, 256>>>(x);
    triplet_kernel<<<NBLK_T, 512>>>(labels, out);
}